// round 17
// baseline (speedup 1.0000x reference)
#include <cuda_runtime.h>
#include <cuda_fp16.h>
#include <math.h>

#define NB 64
#define NL 1024
#define ND 1024
#define SPLIT 32               // kD l-splits (CH_D = 32)
#define CH_D (NL / SPLIT)
#define SPLITE 32              // kE l-splits (32 rows per block)
#define EPSF 1e-15f
#define PROJ_EPS 4e-3f

// ---------------- scratch (device globals) ----------------
__device__ float g_combined[NB * 2 * ND];   // [b,0:D)=mixl, [b,D:2D)=q
__device__ float g_scores[NB * NL];
__device__ float g_aw[NB * NL];
__device__ float g_bt[NB * NL];
__device__ float g_btn[NB];
__device__ float g_u[NB * ND];
__device__ float g_v[NB * ND];
__device__ float g_dl[NB * ND];
__device__ float g_lam[NB * NL];
__device__ float g_part[6 * NB * SPLIT * ND];    // kD partials
__device__ float g_nomp[NB * SPLITE * ND];       // kE nom partials
__device__ __half g_ctxh[(size_t)NB * NL * ND];  // fp16 shadow of ctx (128 MB)

__device__ __forceinline__ float artanh_c(float x) {
    x = fminf(fmaxf(x, -1.0f + 1e-7f), 1.0f - 1e-7f);
    return atanhf(x);
}

// fast block reduction for 1024 threads: warp shuffle + 32-slot smem
__device__ __forceinline__ float bsum1024(float v, float* s32) {
    int lane = threadIdx.x & 31, warp = threadIdx.x >> 5;
#pragma unroll
    for (int o = 16; o > 0; o >>= 1) v += __shfl_xor_sync(0xffffffffu, v, o);
    if (lane == 0) s32[warp] = v;
    __syncthreads();
    if (warp == 0) {
        float w = s32[lane];
#pragma unroll
        for (int o = 16; o > 0; o >>= 1) w += __shfl_xor_sync(0xffffffffu, w, o);
        if (lane == 0) s32[0] = w;
    }
    __syncthreads();
    float r = s32[0];
    __syncthreads();
    return r;
}

__device__ __forceinline__ float bmax1024(float v, float* s32) {
    int lane = threadIdx.x & 31, warp = threadIdx.x >> 5;
#pragma unroll
    for (int o = 16; o > 0; o >>= 1) v = fmaxf(v, __shfl_xor_sync(0xffffffffu, v, o));
    if (lane == 0) s32[warp] = v;
    __syncthreads();
    if (warp == 0) {
        float w = s32[lane];
#pragma unroll
        for (int o = 16; o > 0; o >>= 1) w = fmaxf(w, __shfl_xor_sync(0xffffffffu, w, o));
        if (lane == 0) s32[0] = w;
    }
    __syncthreads();
    float r = s32[0];
    __syncthreads();
    return r;
}

// ---------------- A: q = query @ W_in^T ----------------
__global__ void kA(const float* __restrict__ query, const float* __restrict__ W_in) {
    int b = threadIdx.x;
    int e = blockIdx.x * 4 + threadIdx.y;
    const float4* q4 = (const float4*)(query + (size_t)b * ND);
    const float4* w4 = (const float4*)(W_in + (size_t)e * ND);
    float acc = 0.f;
#pragma unroll 4
    for (int k = 0; k < ND / 4; k++) {
        float4 a = q4[k], w = w4[k];
        acc += a.x * w.x + a.y * w.y + a.z * w.z + a.w * w.w;
    }
    g_combined[(size_t)b * 2 * ND + ND + e] = acc;
}

// ---------------- B: scores + fp16 shadow write  (ascending b) ----------------
__global__ void kB(const float* __restrict__ ctx) {
    __shared__ float sq[ND];
    int b = blockIdx.y;
    int warp = threadIdx.x >> 5, lane = threadIdx.x & 31;
    ((float4*)sq)[threadIdx.x] = ((const float4*)(g_combined + (size_t)b * 2 * ND + ND))[threadIdx.x];
    __syncthreads();
    int l = blockIdx.x * 8 + warp;
    size_t row = ((size_t)(b * NL + l)) * ND;
    const float4* c4 = (const float4*)(ctx + row);
    uint2* h2 = (uint2*)(g_ctxh + row);          // uint2 = 4 halves
    const float4* s4 = (const float4*)sq;
    float acc = 0.f;
#pragma unroll
    for (int k = 0; k < 8; k++) {
        int i = k * 32 + lane;
        float4 cv = c4[i], qv = s4[i];
        acc += cv.x * qv.x + cv.y * qv.y + cv.z * qv.z + cv.w * qv.w;
        union { __half2 h[2]; uint2 u; } pk;
        pk.h[0] = __floats2half2_rn(cv.x, cv.y);
        pk.h[1] = __floats2half2_rn(cv.z, cv.w);
        h2[i] = pk.u;
    }
#pragma unroll
    for (int o = 16; o > 0; o >>= 1) acc += __shfl_down_sync(0xffffffffu, acc, o);
    if (lane == 0) g_scores[b * NL + l] = acc;
}

// ---------------- C: softmax + expmap0/project (aw), bt ----------------
__global__ void kC(const float* __restrict__ dt, const float* __restrict__ cp,
                   const float* __restrict__ ab, float* __restrict__ out_aw) {
    __shared__ float s32[32];
    int b = blockIdx.x, t = threadIdx.x;
    float c = cp[0], sc = sqrtf(c);
    float maxn = (1.0f - PROJ_EPS) / sc;

    float s = g_scores[b * NL + t];
    float mx = bmax1024(s, s32);
    float e = expf(s - mx);
    float sum = bsum1024(e, s32);
    float aw = e / sum;

    float n = fmaxf(sqrtf(bsum1024(aw * aw, s32)), EPSF);
    float awh = tanhf(sc * n) / (sc * n) * aw;
    float nh = fmaxf(sqrtf(bsum1024(awh * awh, s32)), EPSF);
    if (nh > maxn) awh *= maxn / nh;
    g_aw[b * NL + t] = awh;
    out_aw[b * NL + t] = awh;

    float braw = expf(-ab[b] * dt[b * NL + t]);
    float bn = fmaxf(sqrtf(bsum1024(braw * braw, s32)), EPSF);
    float bth = tanhf(sc * bn) / (sc * bn) * braw;
    float bh = fmaxf(sqrtf(bsum1024(bth * bth, s32)), EPSF);
    if (bh > maxn) bth *= maxn / bh;
    g_bt[b * NL + t] = bth;
    if (t == 0) g_btn[b] = fminf(bh, maxn);
}

// ---------------- D1: partial column stats from fp16 ctx (512 thr x half2, descending b) ----
__global__ void __launch_bounds__(512) kD1() {
    __shared__ float sc1[CH_D], sc2[CH_D], sc3[CH_D];
    int b = NB - 1 - blockIdx.y;       // reverse: reuse L2 tail from kB
    int s = blockIdx.x, t = threadIdx.x;
    int l0 = s * CH_D;
    if (t < CH_D) {
        float a = g_aw[b * NL + l0 + t];
        float bt = g_bt[b * NL + l0 + t];
        float a2 = a * a;
        sc1[t] = a2;
        sc2[t] = a2 * bt * bt;
        sc3[t] = a2 * bt;
    }
    __syncthreads();
    const __half2* cb = (const __half2*)(g_ctxh + ((size_t)(b * NL + l0)) * ND) + t;

    float2 sx2 = {0,0}, swx2 = {0,0};
    float2 s2p = {0,0}, s2n = {0,0}, sxp = {0,0}, sxn = {0,0};

#pragma unroll 4
    for (int ll = 0; ll < CH_D; ll++) {
        float2 x = __half22float2(cb[(size_t)ll * (ND / 2)]);
        float c1 = sc1[ll], c2 = sc2[ll], c3 = sc3[ll];
        {
            float x2 = x.x * x.x; float xp = (x.x > 0.f) ? x2 : 0.f; float xm = x2 - xp;
            sx2.x += x2; swx2.x = fmaf(c1, x2, swx2.x);
            s2p.x = fmaf(c2, xp, s2p.x); s2n.x = fmaf(c2, xm, s2n.x);
            sxp.x = fmaf(c3, xp, sxp.x); sxn.x = fmaf(c3, xm, sxn.x);
        }
        {
            float x2 = x.y * x.y; float xp = (x.y > 0.f) ? x2 : 0.f; float xm = x2 - xp;
            sx2.y += x2; swx2.y = fmaf(c1, x2, swx2.y);
            s2p.y = fmaf(c2, xp, s2p.y); s2n.y = fmaf(c2, xm, s2n.y);
            sxp.y = fmaf(c3, xp, sxp.y); sxn.y = fmaf(c3, xm, sxn.y);
        }
    }
    size_t base = ((size_t)(b * SPLIT + s)) * ND;
    size_t stride = (size_t)NB * SPLIT * ND;
    ((float2*)(g_part + 0 * stride + base))[t] = sx2;
    ((float2*)(g_part + 1 * stride + base))[t] = swx2;
    ((float2*)(g_part + 2 * stride + base))[t] = s2p;
    ((float2*)(g_part + 3 * stride + base))[t] = s2n;
    ((float2*)(g_part + 4 * stride + base))[t] = sxp;
    ((float2*)(g_part + 5 * stride + base))[t] = sxn;
}

// ---------------- Df: finalize per-(b,d) scalars u, v, delta ----------------
__global__ void kDf(const float* __restrict__ cp, const float* __restrict__ ae) {
    int b = blockIdx.y;
    int d = blockIdx.x * 256 + threadIdx.x;
    size_t stride = (size_t)NB * SPLIT * ND;
    float sx2 = 0.f, swx2 = 0.f, s2p = 0.f, s2n = 0.f, sxp = 0.f, sxn = 0.f;
#pragma unroll
    for (int s = 0; s < SPLIT; s++) {
        size_t base = ((size_t)(b * SPLIT + s)) * ND + d;
        sx2  += g_part[0 * stride + base];
        swx2 += g_part[1 * stride + base];
        s2p  += g_part[2 * stride + base];
        s2n  += g_part[3 * stride + base];
        sxp  += g_part[4 * stride + base];
        sxn  += g_part[5 * stride + base];
    }

    float c = cp[0], sc = sqrtf(c);
    float maxn = (1.0f - PROJ_EPS) / sc;

    float xn   = fmaxf(sqrtf(sx2), EPSF);
    float wxnr = sqrtf(swx2);
    float wxn  = fmaxf(wxnr, EPSF);
    float s1 = tanhf(wxn / xn * artanh_c(sc * xn)) / (wxn * sc);
    float n1 = fmaxf(fabsf(s1) * wxnr, EPSF);
    float alpha = s1 * (n1 > maxn ? maxn / n1 : 1.0f);
    float nmixr = fabsf(alpha) * wxnr;

    float aeb = ae[b];
    float xn7 = fmaxf(nmixr, EPSF);
    float wxn7 = fmaxf(fabsf(aeb) * nmixr, EPSF);
    float t7 = tanhf(wxn7 / xn7 * artanh_c(sc * xn7)) / (wxn7 * sc);
    float n7 = fmaxf(fabsf(t7 * aeb) * nmixr, EPSF);
    float T = t7 * aeb * alpha * (n7 > maxn ? maxn / n7 : 1.0f);

    float m8r = sqrtf(s2p + s2n);
    float xn8 = g_btn[b];
    float wxn8 = fmaxf(fabsf(T) * m8r, EPSF);
    float t8 = tanhf(wxn8 / xn8 * artanh_c(sc * xn8)) / (wxn8 * sc);
    float dpre = t8 * T;
    float n8 = fmaxf(fabsf(dpre) * m8r, EPSF);
    float dl = dpre * (n8 > maxn ? maxn / n8 : 1.0f);

    float x2 = alpha * alpha * swx2;
    bool pos = (dl > 0.f);
    float S2 = pos ? s2p : s2n;
    float SX = pos ? sxp : sxn;
    float y2 = dl * dl * S2;
    float xy = alpha * dl * SX;
    float A  = 1.0f + 2.0f * c * xy + c * y2;
    float Bc = 1.0f - c * x2;
    float den = fmaxf(1.0f + 2.0f * c * xy + c * c * x2 * y2, EPSF);
    float nn2 = (A * A * x2 + 2.0f * A * Bc * xy + Bc * Bc * y2) / (den * den);
    float n10 = fmaxf(sqrtf(fmaxf(nn2, 0.f)), EPSF);
    float p10 = (n10 > maxn) ? maxn / n10 : 1.0f;

    g_u[b * ND + d]  = p10 * A * alpha / den;
    g_v[b * ND + d]  = p10 * Bc * dl / den;
    g_dl[b * ND + d] = dl;
}

// ---------------- E2 (fused, register-tile): lambda + nom in ONE ctx read -----------------
// Block = 32 rows x 1024 cols; 8 warps, warp owns a 128-col strip, lane owns 4 cols.
// Per 16-row subtile: 16-deep register load burst -> per-row lambda partial (1 shuffle-
// reduce per row per warp) -> barrier -> cross-warp lambda finalize -> barrier -> nom
// accumulated from the SAME registers (no reload, no smem data traffic).
__global__ void __launch_bounds__(256) kE2(const float* __restrict__ cp) {
    __shared__ float sP[8][16];
    __shared__ float saw[32], sbt[32], slam[32];
    int b = blockIdx.y;                 // ascending: reuse L2 tail from kD1
    int s = blockIdx.x, t = threadIdx.x;
    int warp = t >> 5, lane = t & 31;
    int l0 = s * 32;
    float c = cp[0];
    if (t < 32) { saw[t] = g_aw[b * NL + l0 + t]; sbt[t] = g_bt[b * NL + l0 + t]; }

    int d0 = warp * 128 + lane * 4;
    float4 u  = *(const float4*)(g_u  + (size_t)b * ND + d0);
    float4 v  = *(const float4*)(g_v  + (size_t)b * ND + d0);
    float4 dl = *(const float4*)(g_dl + (size_t)b * ND + d0);
    float4 nom = {0, 0, 0, 0};
    const uint2* base = (const uint2*)(g_ctxh + ((size_t)(b * NL + l0)) * ND) + (warp * 32 + lane);
    __syncthreads();

#pragma unroll
    for (int sub = 0; sub < 2; sub++) {
        int r0 = sub * 16;
        uint2 r[16];
#pragma unroll
        for (int i = 0; i < 16; i++)
            r[i] = base[(size_t)(r0 + i) * (ND / 4)];

        // ---- lambda partials: one shuffle-reduce per row per warp ----
#pragma unroll
        for (int i = 0; i < 16; i++) {
            float a = saw[r0 + i], bt = sbt[r0 + i];
            float2 x01 = __half22float2(*(__half2*)&r[i].x);
            float2 x23 = __half22float2(*(__half2*)&r[i].y);
            float g, m, ss = 0.f;
            g = a * bt * x01.x; m = u.x * a * x01.x + ((dl.x * g) > 0.f ? v.x * g : 0.f); ss += m * m;
            g = a * bt * x01.y; m = u.y * a * x01.y + ((dl.y * g) > 0.f ? v.y * g : 0.f); ss += m * m;
            g = a * bt * x23.x; m = u.z * a * x23.x + ((dl.z * g) > 0.f ? v.z * g : 0.f); ss += m * m;
            g = a * bt * x23.y; m = u.w * a * x23.y + ((dl.w * g) > 0.f ? v.w * g : 0.f); ss += m * m;
#pragma unroll
            for (int o = 16; o > 0; o >>= 1) ss += __shfl_xor_sync(0xffffffffu, ss, o);
            if (lane == 0) sP[warp][i] = ss;
        }
        __syncthreads();

        // ---- finalize lambda for these 16 rows ----
        if (t < 16) {
            float tot = 0.f;
#pragma unroll
            for (int w = 0; w < 8; w++) tot += sP[w][t];
            float lam = 2.0f / fmaxf(1.0f - c * tot, EPSF);
            slam[r0 + t] = lam;
            g_lam[b * NL + l0 + r0 + t] = lam;
        }
        __syncthreads();

        // ---- nom accumulate from registers ----
#pragma unroll
        for (int i = 0; i < 16; i++) {
            float a = saw[r0 + i], bt = sbt[r0 + i], lam = slam[r0 + i];
            float2 x01 = __half22float2(*(__half2*)&r[i].x);
            float2 x23 = __half22float2(*(__half2*)&r[i].y);
            float g, m;
            g = a * bt * x01.x; m = u.x * a * x01.x + ((dl.x * g) > 0.f ? v.x * g : 0.f); nom.x = fmaf(lam, m, nom.x);
            g = a * bt * x01.y; m = u.y * a * x01.y + ((dl.y * g) > 0.f ? v.y * g : 0.f); nom.y = fmaf(lam, m, nom.y);
            g = a * bt * x23.x; m = u.z * a * x23.x + ((dl.z * g) > 0.f ? v.z * g : 0.f); nom.z = fmaf(lam, m, nom.z);
            g = a * bt * x23.y; m = u.w * a * x23.y + ((dl.w * g) > 0.f ? v.w * g : 0.f); nom.w = fmaf(lam, m, nom.w);
        }
        __syncthreads();    // protect sP before next subtile writes
    }
    *(float4*)(g_nomp + ((size_t)(b * SPLITE + s)) * ND + d0) = nom;
}

// ---------------- F: midpoint epilogue ----------------
__global__ void kF(const float* __restrict__ cp) {
    __shared__ float s32[32];
    int b = blockIdx.x, t = threadIdx.x;
    float c = cp[0], sc = sqrtf(c);
    float lam = g_lam[b * NL + t];
    float den = bsum1024(lam - 1.0f, s32);
    den = (den >= 0.f) ? fmaxf(den, 1e-10f) : fminf(den, -1e-10f);

    float nom = 0.f;
#pragma unroll
    for (int s = 0; s < SPLITE; s++)
        nom += g_nomp[((size_t)(b * SPLITE + s)) * ND + t];

    float tm = nom / den;
    float nr = sqrtf(bsum1024(tm * tm, s32));
    float n = fmaxf(nr, EPSF);
    float cf = tanhf(0.5f * artanh_c(sc * n)) / (sc * n);
    float nf = fmaxf(fabsf(cf) * nr, EPSF);
    float lc = artanh_c(sc * nf) / (sc * nf);
    g_combined[(size_t)b * 2 * ND + t] = lc * cf * tm;
}

// ---------------- G: out = tanh(combined @ W_out^T) ----------------
__global__ void kG(const float* __restrict__ W_out, float* __restrict__ out) {
    int b = threadIdx.x;
    int d = blockIdx.x * 4 + threadIdx.y;
    const float4* cb4 = (const float4*)(g_combined + (size_t)b * 2 * ND);
    const float4* w4  = (const float4*)(W_out + (size_t)d * 2 * ND);
    float acc = 0.f;
#pragma unroll 4
    for (int k = 0; k < 2 * ND / 4; k++) {
        float4 a = cb4[k], w = w4[k];
        acc += a.x * w.x + a.y * w.y + a.z * w.z + a.w * w.w;
    }
    out[b * ND + d] = tanhf(acc);
}

// ---------------- launch ----------------
extern "C" void kernel_launch(void* const* d_in, const int* in_sizes, int n_in,
                              void* d_out, int out_size) {
    const float* query = (const float*)d_in[0];
    const float* ctx   = (const float*)d_in[1];
    const float* dt    = (const float*)d_in[2];
    const float* cp    = (const float*)d_in[3];
    const float* W_in  = (const float*)d_in[4];
    const float* W_out = (const float*)d_in[5];
    const float* ae    = (const float*)d_in[6];
    const float* ab    = (const float*)d_in[7];
    float* out = (float*)d_out;

    kA <<<ND / 4, dim3(64, 4)>>>(query, W_in);
    kB <<<dim3(NL / 8, NB), 256>>>(ctx);
    kC <<<NB, 1024>>>(dt, cp, ab, out + NB * ND);
    kD1<<<dim3(SPLIT, NB), 512>>>();
    kDf<<<dim3(ND / 256, NB), 256>>>(cp, ae);
    kE2<<<dim3(SPLITE, NB), 256>>>(cp);
    kF <<<NB, 1024>>>(cp);
    kG <<<ND / 4, dim3(64, 4)>>>(W_out, out);
}